// round 1
// baseline (speedup 1.0000x reference)
#include <cuda_runtime.h>
#include <cuda_bf16.h>

// SosModel: 4-section cascaded biquad (direct-form I) along T of x[B,T,C].
// Strategy: overlap-save chunking. Poles have radius <= 0.9, so state from
// more than W=256 samples back contributes < 0.9^256 ~ 2e-12 relative — far
// below the 1e-3 tolerance. Each thread owns one (b, c, chunk) of length
// L=512, warms up over the preceding W samples from zero state, then writes
// its payload. Lane = channel -> fully coalesced 128B warp loads/stores.

#define BB 16
#define TT 32768
#define CC 64
#define SS 4
#define CHUNK_L 512
#define WARM_W 256
#define NCHUNK (TT / CHUNK_L)   // 64

__global__ __launch_bounds__(256, 4)
void sos_biquad_kernel(const float* __restrict__ x,
                       const float* __restrict__ sos,
                       float* __restrict__ out)
{
    const int gtid = blockIdx.x * blockDim.x + threadIdx.x;
    const int gw   = gtid >> 5;          // global warp id: [0, B*2*NCHUNK)
    const int lane = gtid & 31;

    const int chunk = gw % NCHUNK;
    const int bh    = gw / NCHUNK;
    const int half  = bh & 1;
    const int b     = bh >> 1;
    const int c     = half * 32 + lane;

    // Normalized coefficients (a0 == 1 by construction, but normalize anyway).
    float cb0[SS], cb1[SS], cb2[SS], ca1[SS], ca2[SS];
#pragma unroll
    for (int s = 0; s < SS; s++) {
        const float v0 = __ldg(&sos[s * 6 + 0]);
        const float v1 = __ldg(&sos[s * 6 + 1]);
        const float v2 = __ldg(&sos[s * 6 + 2]);
        const float a0 = __ldg(&sos[s * 6 + 3]);
        const float a1 = __ldg(&sos[s * 6 + 4]);
        const float a2 = __ldg(&sos[s * 6 + 5]);
        const float inv = 1.0f / a0;
        cb0[s] = v0 * inv;
        cb1[s] = v1 * inv;
        cb2[s] = v2 * inv;
        ca1[s] = a1 * inv;
        ca2[s] = a2 * inv;
    }

    // Per-section DF-I state (inputs x1,x2 are the previous section's outputs).
    float sx1[SS], sx2[SS], sy1[SS], sy2[SS];
#pragma unroll
    for (int s = 0; s < SS; s++) {
        sx1[s] = 0.f; sx2[s] = 0.f; sy1[s] = 0.f; sy2[s] = 0.f;
    }

    const int t0 = chunk * CHUNK_L;
    int tstart = t0 - WARM_W;
    if (tstart < 0) tstart = 0;       // chunk 0: exact zero initial state
    const int tend = t0 + CHUNK_L;

    const size_t seq_base = (size_t)b * TT * CC + c;
    const float* __restrict__ xp = x + seq_base;
    float* __restrict__ op = out + seq_base;

#pragma unroll 4
    for (int t = tstart; t < tend; t++) {
        float v = __ldg(&xp[(size_t)t * CC]);
#pragma unroll
        for (int s = 0; s < SS; s++) {
            // y = b0*v + b1*x1 + b2*x2 - a1*y1 - a2*y2
            float acc = fmaf(-ca2[s], sy2[s], fmaf(-ca1[s], sy1[s], 0.f));
            acc = fmaf(cb2[s], sx2[s], acc);
            acc = fmaf(cb1[s], sx1[s], acc);
            const float y = fmaf(cb0[s], v, acc);
            sx2[s] = sx1[s];
            sx1[s] = v;
            sy2[s] = sy1[s];
            sy1[s] = y;
            v = y;
        }
        if (t >= t0) {
            op[(size_t)t * CC] = v;
        }
    }
}

extern "C" void kernel_launch(void* const* d_in, const int* in_sizes, int n_in,
                              void* d_out, int out_size)
{
    const float* x   = (const float*)d_in[0];
    const float* sos = (const float*)d_in[1];
    float* out = (float*)d_out;

    // total warps = B * 2 * NCHUNK = 16*2*64 = 2048 -> 256 blocks of 256 threads
    const int total_warps = BB * 2 * NCHUNK;
    const int threads = 256;
    const int blocks = (total_warps * 32) / threads;

    sos_biquad_kernel<<<blocks, threads>>>(x, sos, out);
}

// round 2
// speedup vs baseline: 1.9273x; 1.9273x over previous
#include <cuda_runtime.h>
#include <cuda_bf16.h>

// SosModel: 4-section cascaded biquad along T of x[B,T,C].
// Overlap-save chunking + Direct-Form-II-Transposed sections.
//
// DF2T per section:   y  = b0*x + s1
//                     s1 = b1*x - a1*y + s2
//                     s2 = b2*x - a2*y
// Recurrence-critical path is only 2 FMAs (y -> s1 -> y'), sections pipeline.
//
// Poles: r in (0.5, 0.9). Warm-up W=160: 0.9^160 ~ 5e-8, far below 1e-3 tol
// even with large cascade residues. Each thread owns one (b, c-half, chunk)
// of L=512 payload samples; lane = channel -> coalesced 128B warp accesses.

#define BB 16
#define TT 32768
#define CC 64
#define SS 4
#define CHUNK_L 512
#define WARM_W 160
#define NCHUNK (TT / CHUNK_L)   // 64

__global__ __launch_bounds__(256, 4)
void sos_biquad_kernel(const float* __restrict__ x,
                       const float* __restrict__ sos,
                       float* __restrict__ out)
{
    const int gtid = blockIdx.x * blockDim.x + threadIdx.x;
    const int gw   = gtid >> 5;          // global warp id: [0, B*2*NCHUNK)
    const int lane = gtid & 31;

    const int chunk = gw % NCHUNK;
    const int bh    = gw / NCHUNK;
    const int half  = bh & 1;
    const int b     = bh >> 1;
    const int c     = half * 32 + lane;

    // Normalized coefficients; negate a1/a2 so the loop is pure FMA.
    float cb0[SS], cb1[SS], cb2[SS], na1[SS], na2[SS];
#pragma unroll
    for (int s = 0; s < SS; s++) {
        const float v0 = __ldg(&sos[s * 6 + 0]);
        const float v1 = __ldg(&sos[s * 6 + 1]);
        const float v2 = __ldg(&sos[s * 6 + 2]);
        const float a0 = __ldg(&sos[s * 6 + 3]);
        const float a1 = __ldg(&sos[s * 6 + 4]);
        const float a2 = __ldg(&sos[s * 6 + 5]);
        const float inv = 1.0f / a0;
        cb0[s] = v0 * inv;
        cb1[s] = v1 * inv;
        cb2[s] = v2 * inv;
        na1[s] = -a1 * inv;
        na2[s] = -a2 * inv;
    }

    // DF2T state: 2 registers per section.
    float s1[SS], s2[SS];
#pragma unroll
    for (int s = 0; s < SS; s++) { s1[s] = 0.f; s2[s] = 0.f; }

    const int t0 = chunk * CHUNK_L;
    int tstart = t0 - WARM_W;
    if (tstart < 0) tstart = 0;       // chunk 0: exact zero initial state
    const int tend = t0 + CHUNK_L;

    const size_t seq_base = (size_t)b * TT * CC + c;
    const float* __restrict__ xp = x + seq_base;
    float* __restrict__ op = out + seq_base;

    // ---- warm-up loop: compute state, no stores ----
#pragma unroll 8
    for (int t = tstart; t < t0; t++) {
        float v = xp[(size_t)t * CC];
#pragma unroll
        for (int s = 0; s < SS; s++) {
            const float y  = fmaf(cb0[s], v, s1[s]);
            const float t1 = fmaf(cb1[s], v, s2[s]);
            const float t2 = cb2[s] * v;
            s1[s] = fmaf(na1[s], y, t1);
            s2[s] = fmaf(na2[s], y, t2);
            v = y;
        }
    }

    // ---- payload loop: always store ----
#pragma unroll 8
    for (int t = t0; t < tend; t++) {
        float v = xp[(size_t)t * CC];
#pragma unroll
        for (int s = 0; s < SS; s++) {
            const float y  = fmaf(cb0[s], v, s1[s]);
            const float t1 = fmaf(cb1[s], v, s2[s]);
            const float t2 = cb2[s] * v;
            s1[s] = fmaf(na1[s], y, t1);
            s2[s] = fmaf(na2[s], y, t2);
            v = y;
        }
        op[(size_t)t * CC] = v;
    }
}

extern "C" void kernel_launch(void* const* d_in, const int* in_sizes, int n_in,
                              void* d_out, int out_size)
{
    const float* x   = (const float*)d_in[0];
    const float* sos = (const float*)d_in[1];
    float* out = (float*)d_out;

    const int total_warps = BB * 2 * NCHUNK;   // 2048
    const int threads = 256;
    const int blocks = (total_warps * 32) / threads;  // 256

    sos_biquad_kernel<<<blocks, threads>>>(x, sos, out);
}

// round 3
// speedup vs baseline: 3.2142x; 1.6677x over previous
#include <cuda_runtime.h>
#include <cuda_bf16.h>

// SosModel: 4-section cascaded biquad along T of x[B,T,C].
// Overlap-save chunking + DF2T sections + explicit 16-deep register
// load pipeline (double buffer) so DRAM latency is hidden by MLP=16.

#define BB 16
#define TT 32768
#define CC 64
#define SS 4
#define CHUNK_L 512
#define WARM_W 160              // multiple of U; 0.9^160 ~ 5e-8 truncation
#define NCHUNK (TT / CHUNK_L)   // 64
#define U 16                    // pipeline block

__global__ __launch_bounds__(128, 4)
void sos_biquad_kernel(const float* __restrict__ x,
                       const float* __restrict__ sos,
                       float* __restrict__ out)
{
    const int gtid = blockIdx.x * blockDim.x + threadIdx.x;
    const int gw   = gtid >> 5;          // global warp id: [0, B*2*NCHUNK)
    const int lane = gtid & 31;

    const int chunk = gw % NCHUNK;
    const int bh    = gw / NCHUNK;
    const int half  = bh & 1;
    const int b     = bh >> 1;
    const int c     = half * 32 + lane;

    // Normalized coefficients; negate a1/a2 so the loop is pure FMA.
    float cb0[SS], cb1[SS], cb2[SS], na1[SS], na2[SS];
#pragma unroll
    for (int s = 0; s < SS; s++) {
        const float v0 = __ldg(&sos[s * 6 + 0]);
        const float v1 = __ldg(&sos[s * 6 + 1]);
        const float v2 = __ldg(&sos[s * 6 + 2]);
        const float a0 = __ldg(&sos[s * 6 + 3]);
        const float a1 = __ldg(&sos[s * 6 + 4]);
        const float a2 = __ldg(&sos[s * 6 + 5]);
        const float inv = 1.0f / a0;
        cb0[s] = v0 * inv;
        cb1[s] = v1 * inv;
        cb2[s] = v2 * inv;
        na1[s] = -a1 * inv;
        na2[s] = -a2 * inv;
    }

    // DF2T state: y = b0*x + s1 ; s1 = b1*x - a1*y + s2 ; s2 = b2*x - a2*y
    float st1[SS], st2[SS];
#pragma unroll
    for (int s = 0; s < SS; s++) { st1[s] = 0.f; st2[s] = 0.f; }

    const int t0     = chunk * CHUNK_L;
    const int tstart = (chunk == 0) ? 0 : (t0 - WARM_W);
    const int tend   = t0 + CHUNK_L;

    const size_t seq_base = (size_t)b * TT * CC + c;
    const float* __restrict__ xp = x + seq_base;
    float* __restrict__ op = out + seq_base;

#define SOS_STEP(v)                                          \
    do {                                                     \
        _Pragma("unroll")                                    \
        for (int s = 0; s < SS; s++) {                       \
            const float y  = fmaf(cb0[s], (v), st1[s]);      \
            const float t1 = fmaf(cb1[s], (v), st2[s]);      \
            const float t2 = cb2[s] * (v);                   \
            st1[s] = fmaf(na1[s], y, t1);                    \
            st2[s] = fmaf(na2[s], y, t2);                    \
            (v) = y;                                         \
        }                                                    \
    } while (0)

    // Pipeline prologue: preload first block.
    float buf[U];
#pragma unroll
    for (int i = 0; i < U; i++) buf[i] = xp[(size_t)(tstart + i) * CC];

    // Warm-up blocks (0 or WARM_W/U trips): compute state, no stores,
    // prefetch next block while computing.
    for (int t = tstart; t < t0; t += U) {
        float nbuf[U];
#pragma unroll
        for (int i = 0; i < U; i++) nbuf[i] = xp[(size_t)(t + U + i) * CC];
#pragma unroll
        for (int i = 0; i < U; i++) {
            float v = buf[i];
            SOS_STEP(v);
        }
#pragma unroll
        for (int i = 0; i < U; i++) buf[i] = nbuf[i];
    }

    // Payload blocks except the last: prefetch + compute + store.
    for (int t = t0; t < tend - U; t += U) {
        float nbuf[U];
#pragma unroll
        for (int i = 0; i < U; i++) nbuf[i] = xp[(size_t)(t + U + i) * CC];
#pragma unroll
        for (int i = 0; i < U; i++) {
            float v = buf[i];
            SOS_STEP(v);
            op[(size_t)(t + i) * CC] = v;
        }
#pragma unroll
        for (int i = 0; i < U; i++) buf[i] = nbuf[i];
    }

    // Last payload block: no prefetch (would run past T).
    {
        const int t = tend - U;
#pragma unroll
        for (int i = 0; i < U; i++) {
            float v = buf[i];
            SOS_STEP(v);
            op[(size_t)(t + i) * CC] = v;
        }
    }
#undef SOS_STEP
}

extern "C" void kernel_launch(void* const* d_in, const int* in_sizes, int n_in,
                              void* d_out, int out_size)
{
    const float* x   = (const float*)d_in[0];
    const float* sos = (const float*)d_in[1];
    float* out = (float*)d_out;

    const int total_warps = BB * 2 * NCHUNK;          // 2048
    const int threads = 128;
    const int blocks = (total_warps * 32) / threads;  // 512

    sos_biquad_kernel<<<blocks, threads>>>(x, sos, out);
}